// round 1
// baseline (speedup 1.0000x reference)
#include <cuda_runtime.h>
#include <math.h>

#define BB   8
#define TT   2048
#define DIN  1024
#define HH   64
#define BT   (BB*TT)
#define TS   64
#define SP   68      // padded smem row stride (floats); 68*4=272B, 16B-aligned

// Scratch for projected q,k,v (device globals: allocation-free scratch)
__device__ __align__(16) float g_q[BT*HH];
__device__ __align__(16) float g_k[BT*HH];
__device__ __align__(16) float g_v[BT*HH];

// ---------------------------------------------------------------------------
// Fused QKV projection: [16384,1024] x [1024,64] x3, fp32.
// 64-row tiles, 256 threads, 4x4 micro-tile per thread per matrix.
// x tile stored transposed in smem (outer-product form): 48 FMA per 4 LDS.128.
// ---------------------------------------------------------------------------
#define PKT 32
__global__ __launch_bounds__(256) void proj_kernel(
    const float* __restrict__ x,
    const float* __restrict__ Wq,
    const float* __restrict__ Wk,
    const float* __restrict__ Wv)
{
    __shared__ float xT[PKT][68];       // xT[kk][row]
    __shared__ float ws[3][PKT][64];    // ws[m][kk][col]

    const int tid = threadIdx.x;
    const int m0  = blockIdx.x * 64;
    const int r0  = (tid >> 4) << 2;    // 0..60
    const int c0  = (tid & 15) << 2;    // 0..60

    float acc[3][4][4];
    #pragma unroll
    for (int m = 0; m < 3; m++)
        #pragma unroll
        for (int i = 0; i < 4; i++)
            #pragma unroll
            for (int j = 0; j < 4; j++) acc[m][i][j] = 0.f;

    const float* W[3] = {Wq, Wk, Wv};

    for (int k0 = 0; k0 < DIN; k0 += PKT) {
        // load x tile (64 rows x 32 k) transposed into smem
        #pragma unroll
        for (int u = 0; u < 2; u++) {
            int lin = tid + u * 256;            // 512 float4s
            int row = lin >> 3;                 // 0..63
            int kq  = (lin & 7) << 2;           // 0..28
            float4 v = *(const float4*)(x + (size_t)(m0 + row) * DIN + k0 + kq);
            xT[kq + 0][row] = v.x;
            xT[kq + 1][row] = v.y;
            xT[kq + 2][row] = v.z;
            xT[kq + 3][row] = v.w;
        }
        // load W tiles (32 x 64 each)
        #pragma unroll
        for (int m = 0; m < 3; m++) {
            #pragma unroll
            for (int u = 0; u < 2; u++) {
                int lin = tid + u * 256;        // 512 float4s
                int row = lin >> 4;             // 0..31
                int cq  = (lin & 15) << 2;      // 0..60
                *(float4*)&ws[m][row][cq] =
                    *(const float4*)(W[m] + (size_t)(k0 + row) * HH + cq);
            }
        }
        __syncthreads();
        #pragma unroll
        for (int kk = 0; kk < PKT; kk++) {
            float4 xv = *(const float4*)&xT[kk][r0];
            float xr[4] = {xv.x, xv.y, xv.z, xv.w};
            #pragma unroll
            for (int m = 0; m < 3; m++) {
                float4 wv = *(const float4*)&ws[m][kk][c0];
                float wr[4] = {wv.x, wv.y, wv.z, wv.w};
                #pragma unroll
                for (int i = 0; i < 4; i++)
                    #pragma unroll
                    for (int j = 0; j < 4; j++)
                        acc[m][i][j] += xr[i] * wr[j];
            }
        }
        __syncthreads();
    }

    float* G[3] = {g_q, g_k, g_v};
    #pragma unroll
    for (int m = 0; m < 3; m++)
        #pragma unroll
        for (int i = 0; i < 4; i++) {
            float4 o = make_float4(acc[m][i][0], acc[m][i][1],
                                   acc[m][i][2], acc[m][i][3]);
            *(float4*)(G[m] + (size_t)(m0 + r0 + i) * HH + c0) = o;
        }
}

// ---------------------------------------------------------------------------
// Flash-style causal attention, fp32. NOTE reference role swap:
//   scores[t,s] = (k_t . q_s) * scale,  mask s<=t,  softmax over s,  out = P.V
// One block = one (b, 64-row t-tile). k-tile (scaled) resident, stream q/v
// s-tiles. S via outer product over h (2 LDS.128 : 16 FMA). Online softmax
// with 4 threads/row + shuffles. P.V with 4x4 register accumulators.
// ---------------------------------------------------------------------------
__global__ __launch_bounds__(256) void attn_kernel(float* __restrict__ out)
{
    extern __shared__ float smem[];
    float* kT     = smem;              // [64 h][SP]  (transposed, pre-scaled)
    float* qT     = kT + 64 * SP;      // [64 h][SP]  (transposed)
    float* vs     = qT + 64 * SP;      // [64 s][SP]  (natural)
    float* ss     = vs + 64 * SP;      // [64 t][SP]  S then P
    float* corr_s = ss + 64 * SP;      // [64]
    float* l_s    = corr_s + 64;       // [64]

    const int tid = threadIdx.x;
    const int b   = blockIdx.y;
    const int tt  = gridDim.x - 1 - blockIdx.x;  // heavy tiles launch first
    const int t0  = tt * TS;

    const int r0 = (tid >> 4) << 2;   // t-rows of this thread's micro-tile
    const int c0 = (tid & 15) << 2;   // s-cols (S phase) / h-cols (PV phase)

    // load K tile transposed with softmax scale folded in
    {
        const float* kg = g_k + ((size_t)b * TT + t0) * HH;
        #pragma unroll
        for (int u = 0; u < 4; u++) {
            int lin = tid + u * 256;       // 1024 float4s
            int row = lin >> 4;            // 0..63
            int hq  = (lin & 15) << 2;     // 0..60
            float4 kv = *(const float4*)(kg + row * HH + hq);
            kT[(hq + 0) * SP + row] = kv.x * 0.125f;
            kT[(hq + 1) * SP + row] = kv.y * 0.125f;
            kT[(hq + 2) * SP + row] = kv.z * 0.125f;
            kT[(hq + 3) * SP + row] = kv.w * 0.125f;
        }
    }

    float o[4][4];
    #pragma unroll
    for (int i = 0; i < 4; i++)
        #pragma unroll
        for (int j = 0; j < 4; j++) o[i][j] = 0.f;

    // per-thread online-softmax state (softmax layout: 4 threads per row)
    float mrow = -INFINITY, lrow = 0.f;
    const int srow = tid >> 2;     // 0..63
    const int sg   = tid & 3;      // quarter of the row

    for (int st = 0; st <= tt; st++) {
        const int s0 = st * TS;
        __syncthreads();           // protect qT/vs/ss from previous iteration
        {
            const float* qg = g_q + ((size_t)b * TT + s0) * HH;
            const float* vg = g_v + ((size_t)b * TT + s0) * HH;
            #pragma unroll
            for (int u = 0; u < 4; u++) {
                int lin = tid + u * 256;
                int row = lin >> 4;
                int hq  = (lin & 15) << 2;
                float4 qv = *(const float4*)(qg + row * HH + hq);
                qT[(hq + 0) * SP + row] = qv.x;
                qT[(hq + 1) * SP + row] = qv.y;
                qT[(hq + 2) * SP + row] = qv.z;
                qT[(hq + 3) * SP + row] = qv.w;
                float4 vv = *(const float4*)(vg + row * HH + hq);
                *(float4*)&vs[row * SP + hq] = vv;
            }
        }
        __syncthreads();

        // ---- S = (scaled k) q^T : outer product over h ----
        float acc[4][4];
        #pragma unroll
        for (int i = 0; i < 4; i++)
            #pragma unroll
            for (int j = 0; j < 4; j++) acc[i][j] = 0.f;
        #pragma unroll 16
        for (int h = 0; h < 64; h++) {
            float4 kv = *(const float4*)&kT[h * SP + r0];
            float4 qv = *(const float4*)&qT[h * SP + c0];
            float kr[4] = {kv.x, kv.y, kv.z, kv.w};
            float qr[4] = {qv.x, qv.y, qv.z, qv.w};
            #pragma unroll
            for (int i = 0; i < 4; i++)
                #pragma unroll
                for (int j = 0; j < 4; j++)
                    acc[i][j] += kr[i] * qr[j];
        }
        #pragma unroll
        for (int i = 0; i < 4; i++)
            *(float4*)&ss[(r0 + i) * SP + c0] =
                make_float4(acc[i][0], acc[i][1], acc[i][2], acc[i][3]);
        __syncthreads();

        // ---- online softmax (row = srow, 16 cols per thread) ----
        float v[16];
        #pragma unroll
        for (int u = 0; u < 4; u++) {
            float4 t4 = *(const float4*)&ss[srow * SP + sg * 16 + 4 * u];
            v[4*u+0] = t4.x; v[4*u+1] = t4.y; v[4*u+2] = t4.z; v[4*u+3] = t4.w;
        }
        if (st == tt) {   // causal mask on the diagonal tile
            #pragma unroll
            for (int e = 0; e < 16; e++)
                if (sg * 16 + e > srow) v[e] = -INFINITY;
        }
        float mx = v[0];
        #pragma unroll
        for (int e = 1; e < 16; e++) mx = fmaxf(mx, v[e]);
        mx = fmaxf(mx, __shfl_xor_sync(0xffffffffu, mx, 1));
        mx = fmaxf(mx, __shfl_xor_sync(0xffffffffu, mx, 2));
        float mnew = fmaxf(mrow, mx);
        float sum = 0.f;
        #pragma unroll
        for (int e = 0; e < 16; e++) { v[e] = __expf(v[e] - mnew); sum += v[e]; }
        sum += __shfl_xor_sync(0xffffffffu, sum, 1);
        sum += __shfl_xor_sync(0xffffffffu, sum, 2);
        float cf = __expf(mrow - mnew);
        lrow = lrow * cf + sum;
        mrow = mnew;
        if (sg == 0) { corr_s[srow] = cf; l_s[srow] = lrow; }
        #pragma unroll
        for (int u = 0; u < 4; u++)
            *(float4*)&ss[srow * SP + sg * 16 + 4 * u] =
                make_float4(v[4*u+0], v[4*u+1], v[4*u+2], v[4*u+3]);
        __syncthreads();

        // ---- O = O*corr + P.V ----
        float cfa[4];
        #pragma unroll
        for (int i = 0; i < 4; i++) cfa[i] = corr_s[r0 + i];
        #pragma unroll
        for (int i = 0; i < 4; i++)
            #pragma unroll
            for (int j = 0; j < 4; j++) o[i][j] *= cfa[i];
        #pragma unroll 8
        for (int s = 0; s < 64; s++) {
            float4 vv = *(const float4*)&vs[s * SP + c0];
            float vr[4] = {vv.x, vv.y, vv.z, vv.w};
            float p[4];
            #pragma unroll
            for (int i = 0; i < 4; i++) p[i] = ss[(r0 + i) * SP + s];
            #pragma unroll
            for (int i = 0; i < 4; i++)
                #pragma unroll
                for (int j = 0; j < 4; j++)
                    o[i][j] += p[i] * vr[j];
        }
    }

    // normalize and write out (l_s from last tile is visible: synced before PV)
    #pragma unroll
    for (int i = 0; i < 4; i++) {
        float inv = 1.f / l_s[r0 + i];
        float4 res = make_float4(o[i][0] * inv, o[i][1] * inv,
                                 o[i][2] * inv, o[i][3] * inv);
        *(float4*)(out + ((size_t)b * TT + t0 + r0 + i) * HH + c0) = res;
    }
}

// ---------------------------------------------------------------------------
extern "C" void kernel_launch(void* const* d_in, const int* in_sizes, int n_in,
                              void* d_out, int out_size)
{
    const float* x  = (const float*)d_in[0];
    const float* Wq = (const float*)d_in[1];
    const float* Wk = (const float*)d_in[2];
    const float* Wv = (const float*)d_in[3];
    float* out = (float*)d_out;

    proj_kernel<<<BT / 64, 256>>>(x, Wq, Wk, Wv);

    const int smem_bytes = (4 * 64 * SP + 128) * (int)sizeof(float);  // 70144
    cudaFuncSetAttribute(attn_kernel,
                         cudaFuncAttributeMaxDynamicSharedMemorySize, smem_bytes);
    dim3 grid(TT / TS, BB);
    attn_kernel<<<grid, 256, smem_bytes>>>(out);
}

// round 2
// speedup vs baseline: 1.0783x; 1.0783x over previous
#include <cuda_runtime.h>
#include <math.h>

#define BB   8
#define TT   2048
#define DIN  1024
#define HH   64
#define BT   (BB*TT)
#define TS   64
#define SP   68      // padded smem row stride (floats); 68*4=272B, 16B-aligned

// Scratch for projected q,k,v (device globals: allocation-free scratch)
__device__ __align__(16) float g_q[BT*HH];
__device__ __align__(16) float g_k[BT*HH];
__device__ __align__(16) float g_v[BT*HH];

// ---- packed f32x2 helpers (SASS: FFMA2 / FMUL2, sm_103a) --------------------
typedef unsigned long long ull;

__device__ __forceinline__ ull pack2(float lo, float hi) {
    ull r; asm("mov.b64 %0, {%1, %2};" : "=l"(r) : "f"(lo), "f"(hi)); return r;
}
__device__ __forceinline__ void unpack2(ull v, float& lo, float& hi) {
    asm("mov.b64 {%0, %1}, %2;" : "=f"(lo), "=f"(hi) : "l"(v));
}
__device__ __forceinline__ void ffma2(ull& d, ull a, ull b) {
    asm("fma.rn.f32x2 %0, %1, %2, %0;" : "+l"(d) : "l"(a), "l"(b));
}
__device__ __forceinline__ void fmul2(ull& d, ull a) {
    asm("mul.rn.f32x2 %0, %0, %1;" : "+l"(d) : "l"(a));
}

// ---------------------------------------------------------------------------
// Fused QKV projection: [16384,1024] x [1024,64] x3, fp32 via FFMA2.
// 64-row tiles, 256 threads, 4x4 micro-tile per thread per matrix.
// ---------------------------------------------------------------------------
#define PKT 32
__global__ __launch_bounds__(256) void proj_kernel(
    const float* __restrict__ x,
    const float* __restrict__ Wq,
    const float* __restrict__ Wk,
    const float* __restrict__ Wv)
{
    __shared__ float xT[PKT][68];       // xT[kk][row]
    __shared__ float ws[3][PKT][64];    // ws[m][kk][col]

    const int tid = threadIdx.x;
    const int m0  = blockIdx.x * 64;
    const int r0  = (tid >> 4) << 2;    // 0..60
    const int c0  = (tid & 15) << 2;    // 0..60

    ull acc2[3][4][2];
    #pragma unroll
    for (int m = 0; m < 3; m++)
        #pragma unroll
        for (int i = 0; i < 4; i++) { acc2[m][i][0] = 0ull; acc2[m][i][1] = 0ull; }

    const float* W[3] = {Wq, Wk, Wv};

    for (int k0 = 0; k0 < DIN; k0 += PKT) {
        #pragma unroll
        for (int u = 0; u < 2; u++) {
            int lin = tid + u * 256;
            int row = lin >> 3;
            int kq  = (lin & 7) << 2;
            float4 v = *(const float4*)(x + (size_t)(m0 + row) * DIN + k0 + kq);
            xT[kq + 0][row] = v.x;
            xT[kq + 1][row] = v.y;
            xT[kq + 2][row] = v.z;
            xT[kq + 3][row] = v.w;
        }
        #pragma unroll
        for (int m = 0; m < 3; m++) {
            #pragma unroll
            for (int u = 0; u < 2; u++) {
                int lin = tid + u * 256;
                int row = lin >> 4;
                int cq  = (lin & 15) << 2;
                *(float4*)&ws[m][row][cq] =
                    *(const float4*)(W[m] + (size_t)(k0 + row) * HH + cq);
            }
        }
        __syncthreads();
        #pragma unroll
        for (int kk = 0; kk < PKT; kk++) {
            float4 xv = *(const float4*)&xT[kk][r0];
            ull xd[4] = {pack2(xv.x, xv.x), pack2(xv.y, xv.y),
                         pack2(xv.z, xv.z), pack2(xv.w, xv.w)};
            #pragma unroll
            for (int m = 0; m < 3; m++) {
                float4 wv = *(const float4*)&ws[m][kk][c0];
                ull wp0 = pack2(wv.x, wv.y);
                ull wp1 = pack2(wv.z, wv.w);
                #pragma unroll
                for (int i = 0; i < 4; i++) {
                    ffma2(acc2[m][i][0], xd[i], wp0);
                    ffma2(acc2[m][i][1], xd[i], wp1);
                }
            }
        }
        __syncthreads();
    }

    float* G[3] = {g_q, g_k, g_v};
    #pragma unroll
    for (int m = 0; m < 3; m++)
        #pragma unroll
        for (int i = 0; i < 4; i++) {
            float4 o;
            unpack2(acc2[m][i][0], o.x, o.y);
            unpack2(acc2[m][i][1], o.z, o.w);
            *(float4*)(G[m] + (size_t)(m0 + r0 + i) * HH + c0) = o;
        }
}

// ---------------------------------------------------------------------------
// Flash-style causal attention, fp32 via FFMA2, fused in-register softmax.
//   scores[t,s] = (k_t . q_s) * scale, mask s<=t, softmax over s, out = P.V
// One block = one (b, 64-row t-tile). Row groups = 16 contiguous lanes;
// online-softmax state replicated across the row group via shfl reductions.
// ---------------------------------------------------------------------------
__global__ __launch_bounds__(256) void attn_kernel(float* __restrict__ out)
{
    extern __shared__ float smem[];
    float* kT = smem;              // [64 h][SP]  (transposed, pre-scaled)
    float* qT = kT + 64 * SP;      // [64 h][SP]  (transposed)
    float* vs = qT + 64 * SP;      // [64 s][SP]  (natural)
    float* ss = vs + 64 * SP;      // [64 t][SP]  P tile

    const int tid = threadIdx.x;
    const int b   = blockIdx.y;
    const int tt  = gridDim.x - 1 - blockIdx.x;  // heavy tiles launch first
    const int t0  = tt * TS;

    const int r0 = (tid >> 4) << 2;   // t-rows of this thread's micro-tile
    const int c0 = (tid & 15) << 2;   // s-cols (S phase) / h-cols (PV phase)

    // load K tile transposed with softmax scale folded in
    {
        const float* kg = g_k + ((size_t)b * TT + t0) * HH;
        #pragma unroll
        for (int u = 0; u < 4; u++) {
            int lin = tid + u * 256;
            int row = lin >> 4;
            int hq  = (lin & 15) << 2;
            float4 kv = *(const float4*)(kg + row * HH + hq);
            kT[(hq + 0) * SP + row] = kv.x * 0.125f;
            kT[(hq + 1) * SP + row] = kv.y * 0.125f;
            kT[(hq + 2) * SP + row] = kv.z * 0.125f;
            kT[(hq + 3) * SP + row] = kv.w * 0.125f;
        }
    }

    ull o2[4][2];
    #pragma unroll
    for (int i = 0; i < 4; i++) { o2[i][0] = 0ull; o2[i][1] = 0ull; }
    float m_r[4] = {-INFINITY, -INFINITY, -INFINITY, -INFINITY};
    float l_r[4] = {0.f, 0.f, 0.f, 0.f};

    for (int st = 0; st <= tt; st++) {
        const int s0 = st * TS;
        __syncthreads();           // prev PV done before overwriting qT/vs
        {
            const float* qg = g_q + ((size_t)b * TT + s0) * HH;
            const float* vg = g_v + ((size_t)b * TT + s0) * HH;
            #pragma unroll
            for (int u = 0; u < 4; u++) {
                int lin = tid + u * 256;
                int row = lin >> 4;
                int hq  = (lin & 15) << 2;
                float4 qv = *(const float4*)(qg + row * HH + hq);
                qT[(hq + 0) * SP + row] = qv.x;
                qT[(hq + 1) * SP + row] = qv.y;
                qT[(hq + 2) * SP + row] = qv.z;
                qT[(hq + 3) * SP + row] = qv.w;
                float4 vv = *(const float4*)(vg + row * HH + hq);
                *(float4*)&vs[row * SP + hq] = vv;
            }
        }
        __syncthreads();

        // ---- S = (scaled k) q^T : FFMA2 outer product over h ----
        ull acc2[4][2];
        #pragma unroll
        for (int i = 0; i < 4; i++) { acc2[i][0] = 0ull; acc2[i][1] = 0ull; }
        #pragma unroll 8
        for (int h = 0; h < 64; h++) {
            float4 kv = *(const float4*)&kT[h * SP + r0];
            float4 qv = *(const float4*)&qT[h * SP + c0];
            ull qp0 = pack2(qv.x, qv.y);
            ull qp1 = pack2(qv.z, qv.w);
            ull kd[4] = {pack2(kv.x, kv.x), pack2(kv.y, kv.y),
                         pack2(kv.z, kv.z), pack2(kv.w, kv.w)};
            #pragma unroll
            for (int i = 0; i < 4; i++) {
                ffma2(acc2[i][0], kd[i], qp0);
                ffma2(acc2[i][1], kd[i], qp1);
            }
        }

        // ---- fused online softmax (row group = 16 contiguous lanes) ----
        float sv[4][4];
        #pragma unroll
        for (int i = 0; i < 4; i++) {
            unpack2(acc2[i][0], sv[i][0], sv[i][1]);
            unpack2(acc2[i][1], sv[i][2], sv[i][3]);
        }
        if (st == tt) {   // causal mask on the diagonal tile
            #pragma unroll
            for (int i = 0; i < 4; i++)
                #pragma unroll
                for (int j = 0; j < 4; j++)
                    if (c0 + j > r0 + i) sv[i][j] = -INFINITY;
        }
        float cfa[4];
        #pragma unroll
        for (int i = 0; i < 4; i++) {
            float rmax = fmaxf(fmaxf(sv[i][0], sv[i][1]),
                               fmaxf(sv[i][2], sv[i][3]));
            #pragma unroll
            for (int off = 1; off < 16; off <<= 1)
                rmax = fmaxf(rmax, __shfl_xor_sync(0xffffffffu, rmax, off));
            float mnew = fmaxf(m_r[i], rmax);
            float rs = 0.f;
            #pragma unroll
            for (int j = 0; j < 4; j++) {
                sv[i][j] = __expf(sv[i][j] - mnew);
                rs += sv[i][j];
            }
            #pragma unroll
            for (int off = 1; off < 16; off <<= 1)
                rs += __shfl_xor_sync(0xffffffffu, rs, off);
            float cf = __expf(m_r[i] - mnew);
            l_r[i] = l_r[i] * cf + rs;
            m_r[i] = mnew;
            cfa[i] = cf;
        }
        #pragma unroll
        for (int i = 0; i < 4; i++)
            *(float4*)&ss[(r0 + i) * SP + c0] =
                make_float4(sv[i][0], sv[i][1], sv[i][2], sv[i][3]);
        __syncthreads();

        // ---- O = O*cf + P.V (FFMA2, 4-wide s-steps) ----
        #pragma unroll
        for (int i = 0; i < 4; i++) {
            ull cfp = pack2(cfa[i], cfa[i]);
            fmul2(o2[i][0], cfp);
            fmul2(o2[i][1], cfp);
        }
        #pragma unroll 4
        for (int s4 = 0; s4 < 64; s4 += 4) {
            float p4[4][4];
            float4 v4[4];
            #pragma unroll
            for (int i = 0; i < 4; i++) {
                float4 t4 = *(const float4*)&ss[(r0 + i) * SP + s4];
                p4[i][0] = t4.x; p4[i][1] = t4.y; p4[i][2] = t4.z; p4[i][3] = t4.w;
            }
            #pragma unroll
            for (int u = 0; u < 4; u++)
                v4[u] = *(const float4*)&vs[(s4 + u) * SP + c0];
            #pragma unroll
            for (int u = 0; u < 4; u++) {
                ull vp0 = pack2(v4[u].x, v4[u].y);
                ull vp1 = pack2(v4[u].z, v4[u].w);
                #pragma unroll
                for (int i = 0; i < 4; i++) {
                    ull pd = pack2(p4[i][u], p4[i][u]);
                    ffma2(o2[i][0], pd, vp0);
                    ffma2(o2[i][1], pd, vp1);
                }
            }
        }
    }

    // normalize and write out
    #pragma unroll
    for (int i = 0; i < 4; i++) {
        float inv = 1.f / l_r[i];
        float4 res;
        unpack2(o2[i][0], res.x, res.y);
        unpack2(o2[i][1], res.z, res.w);
        res.x *= inv; res.y *= inv; res.z *= inv; res.w *= inv;
        *(float4*)(out + ((size_t)b * TT + t0 + r0 + i) * HH + c0) = res;
    }
}

// ---------------------------------------------------------------------------
extern "C" void kernel_launch(void* const* d_in, const int* in_sizes, int n_in,
                              void* d_out, int out_size)
{
    const float* x  = (const float*)d_in[0];
    const float* Wq = (const float*)d_in[1];
    const float* Wk = (const float*)d_in[2];
    const float* Wv = (const float*)d_in[3];
    float* out = (float*)d_out;

    proj_kernel<<<BT / 64, 256>>>(x, Wq, Wk, Wv);

    const int smem_bytes = (4 * 64 * SP) * (int)sizeof(float);  // 69632
    cudaFuncSetAttribute(attn_kernel,
                         cudaFuncAttributeMaxDynamicSharedMemorySize, smem_bytes);
    dim3 grid(TT / TS, BB);
    attn_kernel<<<grid, 256, smem_bytes>>>(out);
}

// round 5
// speedup vs baseline: 2.0801x; 1.9290x over previous
#include <cuda_runtime.h>
#include <cuda_bf16.h>
#include <math.h>

#define BB   8
#define TT   2048
#define DIN  1024
#define HH   64
#define BT   (BB*TT)

typedef unsigned int u32;

// Packed bf16x2 hi/lo scratch (q,k,v) and prepped weights.
// layout: [row][hq] u32, hq = h/2 (pair h, h+1), 32 u32 per row.
__device__ __align__(16) u32 g_qh[BT*32];
__device__ __align__(16) u32 g_ql[BT*32];
__device__ __align__(16) u32 g_kh[BT*32];
__device__ __align__(16) u32 g_kl[BT*32];
__device__ __align__(16) u32 g_vh[BT*32];
__device__ __align__(16) u32 g_vl[BT*32];
// W fragment-ready: [n 0..191][kk 0..511] u32 = pack(W[2kk][n], W[2kk+1][n])
__device__ __align__(16) u32 g_wh[192*512];
__device__ __align__(16) u32 g_wl[192*512];

// ---- helpers ---------------------------------------------------------------
__device__ __forceinline__ u32 pkbf(float lo, float hi) {
    u32 r; asm("cvt.rn.bf16x2.f32 %0, %1, %2;" : "=r"(r) : "f"(hi), "f"(lo));
    return r;
}
__device__ __forceinline__ float bfh(float x) {
    return __bfloat162float(__float2bfloat16(x));
}
__device__ __forceinline__ void mma16816(float* c, const u32* a, const u32* b) {
    asm volatile(
        "mma.sync.aligned.m16n8k16.row.col.f32.bf16.bf16.f32 "
        "{%0,%1,%2,%3}, {%4,%5,%6,%7}, {%8,%9}, {%0,%1,%2,%3};"
        : "+f"(c[0]), "+f"(c[1]), "+f"(c[2]), "+f"(c[3])
        : "r"(a[0]), "r"(a[1]), "r"(a[2]), "r"(a[3]), "r"(b[0]), "r"(b[1]));
}

// ---------------------------------------------------------------------------
// Prep: W -> bf16 hi/lo packed, fragment-ready (pairs along k for fixed n).
// ---------------------------------------------------------------------------
__global__ __launch_bounds__(256) void prep_w_kernel(
    const float* __restrict__ Wq, const float* __restrict__ Wk,
    const float* __restrict__ Wv)
{
    int idx = blockIdx.x * 256 + threadIdx.x;     // 98304 tasks
    int n = idx % 192, kk = idx / 192;
    const float* W = (n < 64) ? Wq : ((n < 128) ? Wk : Wv);
    int col = n & 63;
    float w0 = W[(size_t)(2 * kk) * HH + col];
    float w1 = W[(size_t)(2 * kk + 1) * HH + col];
    float h0 = bfh(w0), h1 = bfh(w1);
    g_wh[n * 512 + kk] = pkbf(h0, h1);
    g_wl[n * 512 + kk] = pkbf(w0 - h0, w1 - h1);
}

// ---------------------------------------------------------------------------
// Fused QKV projection via mma.sync bf16x3.
// CTA: 64 rows x 192 cols, K=1024 in 16 chunks of 64.
// 8 warps: slab=w/2 (16 rows), half=w&1 (96 cols = 12 n-tiles).
// Epilogue writes packed bf16 hi/lo q/k/v (K pre-scaled 1/8).
// ---------------------------------------------------------------------------
#define PST 36   // smem row stride (u32) -> conflict-free fragment loads
#define PROJ_SMEM_U32 (2304*2 + 6912*2)   // 18432 u32 = 73728 B

__global__ __launch_bounds__(256) void proj_kernel(const float* __restrict__ x)
{
    extern __shared__ u32 sm[];
    u32* sxh = sm;              // [64][36]
    u32* sxl = sm + 2304;
    u32* swh = sm + 4608;       // [192][36]
    u32* swl = sm + 11520;

    const int tid  = threadIdx.x;
    const int wid  = tid >> 5, lane = tid & 31;
    const int slab = wid >> 1, half = wid & 1;
    const int rr   = lane >> 2, q = lane & 3;
    const int m0   = blockIdx.x * 64;

    float acc[12][4];
    #pragma unroll
    for (int i = 0; i < 12; i++)
        #pragma unroll
        for (int j = 0; j < 4; j++) acc[i][j] = 0.f;

    for (int c = 0; c < 16; c++) {
        const int k0 = c * 64, kk0 = c * 32;
        __syncthreads();
        // X chunk -> bf16 hi/lo packed
        #pragma unroll
        for (int u = 0; u < 4; u++) {
            int idx = tid + u * 256;          // 1024 float4 tasks
            int row = idx >> 4, f4 = idx & 15;
            float4 v = *(const float4*)(x + (size_t)(m0 + row) * DIN + k0 + 4 * f4);
            float h0 = bfh(v.x), h1 = bfh(v.y), h2 = bfh(v.z), h3 = bfh(v.w);
            sxh[row * PST + 2 * f4]     = pkbf(h0, h1);
            sxh[row * PST + 2 * f4 + 1] = pkbf(h2, h3);
            sxl[row * PST + 2 * f4]     = pkbf(v.x - h0, v.y - h1);
            sxl[row * PST + 2 * f4 + 1] = pkbf(v.z - h2, v.w - h3);
        }
        // W chunk copy (already packed)
        #pragma unroll
        for (int u = 0; u < 6; u++) {
            int idx = tid + u * 256;          // 1536 uint4 tasks
            int n = idx >> 3, kq4 = (idx & 7) * 4;
            uint4 a = *(const uint4*)&g_wh[n * 512 + kk0 + kq4];
            swh[n * PST + kq4]     = a.x; swh[n * PST + kq4 + 1] = a.y;
            swh[n * PST + kq4 + 2] = a.z; swh[n * PST + kq4 + 3] = a.w;
            uint4 b = *(const uint4*)&g_wl[n * 512 + kk0 + kq4];
            swl[n * PST + kq4]     = b.x; swl[n * PST + kq4 + 1] = b.y;
            swl[n * PST + kq4 + 2] = b.z; swl[n * PST + kq4 + 3] = b.w;
        }
        __syncthreads();

        const int row = slab * 16 + rr;
        #pragma unroll
        for (int kt = 0; kt < 4; kt++) {
            u32 ah[4], al[4];
            ah[0] = sxh[row * PST + 8 * kt + q];
            ah[1] = sxh[(row + 8) * PST + 8 * kt + q];
            ah[2] = sxh[row * PST + 8 * kt + q + 4];
            ah[3] = sxh[(row + 8) * PST + 8 * kt + q + 4];
            al[0] = sxl[row * PST + 8 * kt + q];
            al[1] = sxl[(row + 8) * PST + 8 * kt + q];
            al[2] = sxl[row * PST + 8 * kt + q + 4];
            al[3] = sxl[(row + 8) * PST + 8 * kt + q + 4];
            #pragma unroll
            for (int nt = 0; nt < 12; nt++) {
                int n = half * 96 + nt * 8 + rr;
                u32 bh[2] = {swh[n * PST + 8 * kt + q], swh[n * PST + 8 * kt + q + 4]};
                u32 bl[2] = {swl[n * PST + 8 * kt + q], swl[n * PST + 8 * kt + q + 4]};
                mma16816(acc[nt], ah, bh);
                mma16816(acc[nt], ah, bl);
                mma16816(acc[nt], al, bh);
            }
        }
    }

    // epilogue: split to bf16 hi/lo packed q/k/v; fold 0.125 into K
    u32* const GH[3] = {g_qh, g_kh, g_vh};
    u32* const GL[3] = {g_ql, g_kl, g_vl};
    const int row0 = m0 + slab * 16 + rr;
    #pragma unroll
    for (int nt = 0; nt < 12; nt++) {
        int colb = half * 96 + nt * 8;
        int mat = colb >> 6;
        int hqb = (colb & 63) >> 1;
        float s = (mat == 1) ? 0.125f : 1.f;
        float a0 = acc[nt][0] * s, a1 = acc[nt][1] * s;
        float a2 = acc[nt][2] * s, a3 = acc[nt][3] * s;
        float h0 = bfh(a0), h1 = bfh(a1), h2 = bfh(a2), h3 = bfh(a3);
        GH[mat][(size_t)row0 * 32 + hqb + q]       = pkbf(h0, h1);
        GL[mat][(size_t)row0 * 32 + hqb + q]       = pkbf(a0 - h0, a1 - h1);
        GH[mat][(size_t)(row0 + 8) * 32 + hqb + q] = pkbf(h2, h3);
        GL[mat][(size_t)(row0 + 8) * 32 + hqb + q] = pkbf(a2 - h2, a3 - h3);
    }
}

// ---------------------------------------------------------------------------
// Flash attention via mma.sync bf16x3.
//   scores[t,s] = (k_t . q_s)/8, mask s<=t, softmax over s, out = P.V
// t-tile 64. 8 warps: slab (16 t-rows) x half (32 s-cols). Independent
// per-warp online softmax; halves merged once at the end.
// ---------------------------------------------------------------------------
#define ATTN_SMEM_U32 (13824 + 256)   // 56320 B

__global__ __launch_bounds__(256) void attn_kernel(float* __restrict__ out)
{
    extern __shared__ u32 sm[];
    u32* skh = sm;              // K  [64 t][36]
    u32* skl = sm + 2304;
    u32* sqh = sm + 4608;       // Q  [64 s][36]
    u32* sql = sm + 6912;
    u32* svh = sm + 9216;       // Vt [64 h][36] (pairs along s)
    u32* svl = sm + 11520;
    float* mlbuf = (float*)(sm + 13824);   // [8 warp][16 row][m,l]
    float* obuf  = (float*)(sm + 4608);    // 64x64 f32, used after loop

    const int tid  = threadIdx.x;
    const int wid  = tid >> 5, lane = tid & 31;
    const int slab = wid >> 1, half = wid & 1;
    const int rr   = lane >> 2, q = lane & 3;
    const int b    = blockIdx.y;
    const int tt   = gridDim.x - 1 - blockIdx.x;
    const int t0   = tt * 64;

    // K tile (resident)
    {
        const u32* kh = g_kh + ((size_t)b * TT + t0) * 32;
        const u32* kl = g_kl + ((size_t)b * TT + t0) * 32;
        #pragma unroll
        for (int u = 0; u < 8; u++) {
            int idx = tid + u * 256;
            int row = idx >> 5, kk = idx & 31;
            skh[row * PST + kk] = kh[row * 32 + kk];
            skl[row * PST + kk] = kl[row * 32 + kk];
        }
    }

    float o[8][4];
    #pragma unroll
    for (int i = 0; i < 8; i++)
        #pragma unroll
        for (int j = 0; j < 4; j++) o[i][j] = 0.f;
    float m_lo = -INFINITY, m_hi = -INFINITY, l_lo = 0.f, l_hi = 0.f;

    for (int st = 0; st <= tt; st++) {
        const int s0 = st * 64;
        __syncthreads();
        // Q tile
        {
            const u32* qh = g_qh + ((size_t)b * TT + s0) * 32;
            const u32* ql = g_ql + ((size_t)b * TT + s0) * 32;
            #pragma unroll
            for (int u = 0; u < 8; u++) {
                int idx = tid + u * 256;
                int row = idx >> 5, kk = idx & 31;
                sqh[row * PST + kk] = qh[row * 32 + kk];
                sql[row * PST + kk] = ql[row * 32 + kk];
            }
        }
        // V tile transposed to [h][s/2] pairs
        {
            const u32* vh = g_vh + ((size_t)b * TT + s0) * 32;
            const u32* vl = g_vl + ((size_t)b * TT + s0) * 32;
            #pragma unroll
            for (int u = 0; u < 4; u++) {
                int idx = tid + u * 256;
                int hq = idx & 31, sp = idx >> 5;
                u32 A = vh[(2 * sp) * 32 + hq], Bv = vh[(2 * sp + 1) * 32 + hq];
                svh[(2 * hq) * PST + sp]     = __byte_perm(A, Bv, 0x5410);
                svh[(2 * hq + 1) * PST + sp] = __byte_perm(A, Bv, 0x7632);
                A = vl[(2 * sp) * 32 + hq]; Bv = vl[(2 * sp + 1) * 32 + hq];
                svl[(2 * hq) * PST + sp]     = __byte_perm(A, Bv, 0x5410);
                svl[(2 * hq + 1) * PST + sp] = __byte_perm(A, Bv, 0x7632);
            }
        }
        __syncthreads();

        // ---- S = K.Q^T (scaled) ----
        float sacc[4][4];
        #pragma unroll
        for (int i = 0; i < 4; i++)
            #pragma unroll
            for (int j = 0; j < 4; j++) sacc[i][j] = 0.f;
        const int trow = slab * 16 + rr;
        #pragma unroll
        for (int kt = 0; kt < 4; kt++) {
            u32 ah[4], al[4];
            ah[0] = skh[trow * PST + 8 * kt + q];
            ah[1] = skh[(trow + 8) * PST + 8 * kt + q];
            ah[2] = skh[trow * PST + 8 * kt + q + 4];
            ah[3] = skh[(trow + 8) * PST + 8 * kt + q + 4];
            al[0] = skl[trow * PST + 8 * kt + q];
            al[1] = skl[(trow + 8) * PST + 8 * kt + q];
            al[2] = skl[trow * PST + 8 * kt + q + 4];
            al[3] = skl[(trow + 8) * PST + 8 * kt + q + 4];
            #pragma unroll
            for (int nt = 0; nt < 4; nt++) {
                int n = half * 32 + nt * 8 + rr;
                u32 bh[2] = {sqh[n * PST + 8 * kt + q], sqh[n * PST + 8 * kt + q + 4]};
                u32 bl[2] = {sql[n * PST + 8 * kt + q], sql[n * PST + 8 * kt + q + 4]};
                mma16816(sacc[nt], ah, bh);
                mma16816(sacc[nt], ah, bl);
                mma16816(sacc[nt], al, bh);
            }
        }

        // causal mask on diagonal tile
        if (st == tt) {
            int tlo = t0 + slab * 16 + rr, thi = tlo + 8;
            #pragma unroll
            for (int nt = 0; nt < 4; nt++) {
                int sc = s0 + half * 32 + nt * 8 + 2 * q;
                if (sc > tlo)     sacc[nt][0] = -INFINITY;
                if (sc + 1 > tlo) sacc[nt][1] = -INFINITY;
                if (sc > thi)     sacc[nt][2] = -INFINITY;
                if (sc + 1 > thi) sacc[nt][3] = -INFINITY;
            }
        }

        // ---- online softmax (per warp-half, rows r and r+8) ----
        float mx0 = -INFINITY, mx1 = -INFINITY;
        #pragma unroll
        for (int nt = 0; nt < 4; nt++) {
            mx0 = fmaxf(mx0, fmaxf(sacc[nt][0], sacc[nt][1]));
            mx1 = fmaxf(mx1, fmaxf(sacc[nt][2], sacc[nt][3]));
        }
        mx0 = fmaxf(mx0, __shfl_xor_sync(0xffffffffu, mx0, 1));
        mx0 = fmaxf(mx0, __shfl_xor_sync(0xffffffffu, mx0, 2));
        mx1 = fmaxf(mx1, __shfl_xor_sync(0xffffffffu, mx1, 1));
        mx1 = fmaxf(mx1, __shfl_xor_sync(0xffffffffu, mx1, 2));
        float mn0 = fmaxf(m_lo, mx0), mn1 = fmaxf(m_hi, mx1);
        float sum0 = 0.f, sum1 = 0.f;
        #pragma unroll
        for (int nt = 0; nt < 4; nt++) {
            sacc[nt][0] = __expf(fmaxf(sacc[nt][0] - mn0, -88.f));
            sacc[nt][1] = __expf(fmaxf(sacc[nt][1] - mn0, -88.f));
            sacc[nt][2] = __expf(fmaxf(sacc[nt][2] - mn1, -88.f));
            sacc[nt][3] = __expf(fmaxf(sacc[nt][3] - mn1, -88.f));
            sum0 += sacc[nt][0] + sacc[nt][1];
            sum1 += sacc[nt][2] + sacc[nt][3];
        }
        sum0 += __shfl_xor_sync(0xffffffffu, sum0, 1);
        sum0 += __shfl_xor_sync(0xffffffffu, sum0, 2);
        sum1 += __shfl_xor_sync(0xffffffffu, sum1, 1);
        sum1 += __shfl_xor_sync(0xffffffffu, sum1, 2);
        float cf0 = __expf(fmaxf(m_lo - mn0, -88.f));
        float cf1 = __expf(fmaxf(m_hi - mn1, -88.f));
        l_lo = l_lo * cf0 + sum0; l_hi = l_hi * cf1 + sum1;
        m_lo = mn0; m_hi = mn1;
        #pragma unroll
        for (int nt = 0; nt < 8; nt++) {
            o[nt][0] *= cf0; o[nt][1] *= cf0;
            o[nt][2] *= cf1; o[nt][3] *= cf1;
        }

        // ---- P fragments (in-register, bf16 hi/lo split) ----
        u32 pah[2][4], pal[2][4];
        #pragma unroll
        for (int kp = 0; kp < 2; kp++) {
            float p00 = sacc[2*kp][0],   p01 = sacc[2*kp][1];
            float p02 = sacc[2*kp][2],   p03 = sacc[2*kp][3];
            float p10 = sacc[2*kp+1][0], p11 = sacc[2*kp+1][1];
            float p12 = sacc[2*kp+1][2], p13 = sacc[2*kp+1][3];
            float h00 = bfh(p00), h01 = bfh(p01), h02 = bfh(p02), h03 = bfh(p03);
            float h10 = bfh(p10), h11 = bfh(p11), h12 = bfh(p12), h13 = bfh(p13);
            pah[kp][0] = pkbf(h00, h01);
            pah[kp][1] = pkbf(h02, h03);
            pah[kp][2] = pkbf(h10, h11);
            pah[kp][3] = pkbf(h12, h13);
            pal[kp][0] = pkbf(p00 - h00, p01 - h01);
            pal[kp][1] = pkbf(p02 - h02, p03 - h03);
            pal[kp][2] = pkbf(p10 - h10, p11 - h11);
            pal[kp][3] = pkbf(p12 - h12, p13 - h13);
        }

        // ---- O += P.V ----
        #pragma unroll
        for (int kp = 0; kp < 2; kp++) {
            #pragma unroll
            for (int nt = 0; nt < 8; nt++) {
                int n = nt * 8 + rr;
                int spb = 8 * kp + q + half * 16;
                u32 bh[2] = {svh[n * PST + spb], svh[n * PST + spb + 4]};
                u32 bl[2] = {svl[n * PST + spb], svl[n * PST + spb + 4]};
                mma16816(o[nt], pah[kp], bh);
                mma16816(o[nt], pah[kp], bl);
                mma16816(o[nt], pal[kp], bh);
            }
        }
    }

    // ---- merge the two column-halves ----
    __syncthreads();
    if (q == 0) {
        int base = (slab * 2 + half) * 16;
        mlbuf[(base + rr) * 2]         = m_lo;
        mlbuf[(base + rr) * 2 + 1]     = l_lo;
        mlbuf[(base + rr + 8) * 2]     = m_hi;
        mlbuf[(base + rr + 8) * 2 + 1] = l_hi;
    }
    __syncthreads();
    int ob = (slab * 2 + (1 - half)) * 16;
    float mo0 = mlbuf[(ob + rr) * 2],     lo0 = mlbuf[(ob + rr) * 2 + 1];
    float mo1 = mlbuf[(ob + rr + 8) * 2], lo1 = mlbuf[(ob + rr + 8) * 2 + 1];
    float M0 = fmaxf(m_lo, mo0), M1 = fmaxf(m_hi, mo1);
    float f0 = __expf(fmaxf(m_lo - M0, -88.f));
    float f1 = __expf(fmaxf(m_hi - M1, -88.f));
    float g0 = __expf(fmaxf(mo0 - M0, -88.f));
    float g1 = __expf(fmaxf(mo1 - M1, -88.f));
    float L0 = l_lo * f0 + lo0 * g0;
    float L1 = l_hi * f1 + lo1 * g1;
    #pragma unroll
    for (int nt = 0; nt < 8; nt++) {
        o[nt][0] *= f0; o[nt][1] *= f0;
        o[nt][2] *= f1; o[nt][3] *= f1;
    }
    if (half == 1) {
        #pragma unroll
        for (int nt = 0; nt < 8; nt++) {
            int cb = nt * 8 + 2 * q;
            obuf[(slab * 16 + rr) * 64 + cb]         = o[nt][0];
            obuf[(slab * 16 + rr) * 64 + cb + 1]     = o[nt][1];
            obuf[(slab * 16 + rr + 8) * 64 + cb]     = o[nt][2];
            obuf[(slab * 16 + rr + 8) * 64 + cb + 1] = o[nt][3];
        }
    }
    __syncthreads();
    if (half == 0) {
        float i0 = 1.f / L0, i1 = 1.f / L1;
        size_t rb = ((size_t)b * TT + t0 + slab * 16 + rr) * 64;
        #pragma unroll
        for (int nt = 0; nt < 8; nt++) {
            int cb = nt * 8 + 2 * q;
            float2 r1;
            r1.x = (o[nt][0] + obuf[(slab * 16 + rr) * 64 + cb]) * i0;
            r1.y = (o[nt][1] + obuf[(slab * 16 + rr) * 64 + cb + 1]) * i0;
            *(float2*)(out + rb + cb) = r1;
            float2 r2;
            r2.x = (o[nt][2] + obuf[(slab * 16 + rr + 8) * 64 + cb]) * i1;
            r2.y = (o[nt][3] + obuf[(slab * 16 + rr + 8) * 64 + cb + 1]) * i1;
            *(float2*)(out + rb + 8 * 64 + cb) = r2;
        }
    }
}

// ---------------------------------------------------------------------------
extern "C" void kernel_launch(void* const* d_in, const int* in_sizes, int n_in,
                              void* d_out, int out_size)
{
    const float* x  = (const float*)d_in[0];
    const float* Wq = (const float*)d_in[1];
    const float* Wk = (const float*)d_in[2];
    const float* Wv = (const float*)d_in[3];
    float* out = (float*)d_out;

    prep_w_kernel<<<384, 256>>>(Wq, Wk, Wv);

    cudaFuncSetAttribute(proj_kernel,
                         cudaFuncAttributeMaxDynamicSharedMemorySize,
                         PROJ_SMEM_U32 * 4);
    proj_kernel<<<BT / 64, 256, PROJ_SMEM_U32 * 4>>>(x);

    cudaFuncSetAttribute(attn_kernel,
                         cudaFuncAttributeMaxDynamicSharedMemorySize,
                         ATTN_SMEM_U32 * 4);
    dim3 grid(TT / 64, BB);
    attn_kernel<<<grid, 256, ATTN_SMEM_U32 * 4>>>(out);
}

// round 8
// speedup vs baseline: 2.5787x; 1.2397x over previous
#include <cuda_runtime.h>
#include <cuda_bf16.h>
#include <math.h>

#define BB   8
#define TT   2048
#define DIN  1024
#define HH   64
#define BT   (BB*TT)
#define PST  36      // smem row stride in u32 (144B) -> conflict-free ldmatrix

typedef unsigned int u32;

// Packed bf16x2 hi/lo scratch (q,k,v) and prepped weights.
// layout: [row][hq] u32, hq = h/2, 32 u32 per row.
__device__ __align__(16) u32 g_qh[BT*32];
__device__ __align__(16) u32 g_ql[BT*32];
__device__ __align__(16) u32 g_kh[BT*32];
__device__ __align__(16) u32 g_kl[BT*32];
__device__ __align__(16) u32 g_vh[BT*32];
__device__ __align__(16) u32 g_vl[BT*32];
// V transposed for attention: [b][h 0..63][sp 0..1023], u32 = pack(v[2sp][h], v[2sp+1][h])
__device__ __align__(16) u32 g_vth[BB*64*1024];
__device__ __align__(16) u32 g_vtl[BB*64*1024];
// W fragment-ready: [n 0..191][kk 0..511] u32 = pack(W[2kk][n], W[2kk+1][n])
__device__ __align__(16) u32 g_wh[192*512];
__device__ __align__(16) u32 g_wl[192*512];

// ---- helpers ---------------------------------------------------------------
__device__ __forceinline__ u32 pkbf(float lo, float hi) {
    u32 r; asm("cvt.rn.bf16x2.f32 %0, %1, %2;" : "=r"(r) : "f"(hi), "f"(lo));
    return r;
}
__device__ __forceinline__ float bfh(float x) {
    return __bfloat162float(__float2bfloat16(x));
}
__device__ __forceinline__ void mma16816(float* c, const u32* a, const u32* b) {
    asm volatile(
        "mma.sync.aligned.m16n8k16.row.col.f32.bf16.bf16.f32 "
        "{%0,%1,%2,%3}, {%4,%5,%6,%7}, {%8,%9}, {%0,%1,%2,%3};"
        : "+f"(c[0]), "+f"(c[1]), "+f"(c[2]), "+f"(c[3])
        : "r"(a[0]), "r"(a[1]), "r"(a[2]), "r"(a[3]), "r"(b[0]), "r"(b[1]));
}
__device__ __forceinline__ void ldm_x4(u32* r, u32 addr) {
    asm volatile("ldmatrix.sync.aligned.m8n8.x4.shared.b16 {%0,%1,%2,%3}, [%4];"
        : "=r"(r[0]), "=r"(r[1]), "=r"(r[2]), "=r"(r[3]) : "r"(addr));
}
// NON-trans x2: lane L of each 8x8 gets M[row=L/4][col pair L%4] — matches our
// n-major (Q/W) and h-major (Vt) smem layouts directly.
__device__ __forceinline__ void ldm_x2(u32* r, u32 addr) {
    asm volatile("ldmatrix.sync.aligned.m8n8.x2.shared.b16 {%0,%1}, [%2];"
        : "=r"(r[0]), "=r"(r[1]) : "r"(addr));
}
__device__ __forceinline__ void cp16(u32 smem, const void* g) {
    asm volatile("cp.async.cg.shared.global [%0], [%1], 16;" :: "r"(smem), "l"(g));
}
__device__ __forceinline__ void cp_commit() {
    asm volatile("cp.async.commit_group;" ::: "memory");
}
__device__ __forceinline__ void cp_wait0() {
    asm volatile("cp.async.wait_group 0;" ::: "memory");
}
__device__ __forceinline__ u32 smem_u32(const void* p) {
    u32 a;
    asm("{ .reg .u64 t; cvta.to.shared.u64 t, %1; cvt.u32.u64 %0, t; }"
        : "=r"(a) : "l"(p));
    return a;
}

// ---------------------------------------------------------------------------
// Prep: W -> bf16 hi/lo packed, fragment-ready.
// ---------------------------------------------------------------------------
__global__ __launch_bounds__(256) void prep_w_kernel(
    const float* __restrict__ Wq, const float* __restrict__ Wk,
    const float* __restrict__ Wv)
{
    int idx = blockIdx.x * 256 + threadIdx.x;
    int n = idx % 192, kk = idx / 192;
    const float* W = (n < 64) ? Wq : ((n < 128) ? Wk : Wv);
    int col = n & 63;
    float w0 = W[(size_t)(2 * kk) * HH + col];
    float w1 = W[(size_t)(2 * kk + 1) * HH + col];
    float h0 = bfh(w0), h1 = bfh(w1);
    g_wh[n * 512 + kk] = pkbf(h0, h1);
    g_wl[n * 512 + kk] = pkbf(w0 - h0, w1 - h1);
}

// ---------------------------------------------------------------------------
// Fused QKV projection via mma.sync bf16x3 (ldmatrix fragment loads).
// ---------------------------------------------------------------------------
#define PROJ_SMEM_U32 (2304*2 + 6912*2)

__global__ __launch_bounds__(256) void proj_kernel(const float* __restrict__ x)
{
    extern __shared__ u32 sm[];
    u32* sxh = sm;              // [64][36]
    u32* sxl = sm + 2304;
    u32* swh = sm + 4608;       // [192][36]
    u32* swl = sm + 11520;

    const int tid  = threadIdx.x;
    const int wid  = tid >> 5, lane = tid & 31;
    const int slab = wid >> 1, half = wid & 1;
    const int rr   = lane >> 2, q = lane & 3;
    const int m0   = blockIdx.x * 64;

    const int lane7 = lane & 7;
    const int arow  = lane7 + (lane & 8);
    const int acx4  = (lane & 16) ? 16 : 0;
    const int bex4  = (lane & 8) ? 16 : 0;
    const u32 sbx = smem_u32(sm);
    const u32 aH = sbx + ((slab * 16 + arow) * PST) * 4 + acx4;
    const u32 aL = aH + 2304 * 4;
    const u32 bH = sbx + (4608 + (half * 96 + lane7) * PST) * 4 + bex4;
    const u32 bL = bH + 6912 * 4;

    float acc[12][4];
    #pragma unroll
    for (int i = 0; i < 12; i++)
        #pragma unroll
        for (int j = 0; j < 4; j++) acc[i][j] = 0.f;

    for (int c = 0; c < 16; c++) {
        const int k0 = c * 64, kk0 = c * 32;
        __syncthreads();
        // X chunk -> bf16 hi/lo packed
        #pragma unroll
        for (int u = 0; u < 4; u++) {
            int idx = tid + u * 256;
            int row = idx >> 4, f4 = idx & 15;
            float4 v = *(const float4*)(x + (size_t)(m0 + row) * DIN + k0 + 4 * f4);
            float h0 = bfh(v.x), h1 = bfh(v.y), h2 = bfh(v.z), h3 = bfh(v.w);
            sxh[row * PST + 2 * f4]     = pkbf(h0, h1);
            sxh[row * PST + 2 * f4 + 1] = pkbf(h2, h3);
            sxl[row * PST + 2 * f4]     = pkbf(v.x - h0, v.y - h1);
            sxl[row * PST + 2 * f4 + 1] = pkbf(v.z - h2, v.w - h3);
        }
        // W chunk copy (already packed)
        #pragma unroll
        for (int u = 0; u < 6; u++) {
            int idx = tid + u * 256;
            int n = idx >> 3, kq4 = (idx & 7) * 4;
            uint4 a = *(const uint4*)&g_wh[n * 512 + kk0 + kq4];
            swh[n * PST + kq4]     = a.x; swh[n * PST + kq4 + 1] = a.y;
            swh[n * PST + kq4 + 2] = a.z; swh[n * PST + kq4 + 3] = a.w;
            uint4 b = *(const uint4*)&g_wl[n * 512 + kk0 + kq4];
            swl[n * PST + kq4]     = b.x; swl[n * PST + kq4 + 1] = b.y;
            swl[n * PST + kq4 + 2] = b.z; swl[n * PST + kq4 + 3] = b.w;
        }
        __syncthreads();

        #pragma unroll
        for (int kt = 0; kt < 4; kt++) {
            u32 ah[4], al[4];
            ldm_x4(ah, aH + kt * 32);
            ldm_x4(al, aL + kt * 32);
            #pragma unroll
            for (int nt = 0; nt < 12; nt++) {
                u32 bh[2], bl[2];
                ldm_x2(bh, bH + nt * (8 * PST * 4) + kt * 32);
                ldm_x2(bl, bL + nt * (8 * PST * 4) + kt * 32);
                mma16816(acc[nt], ah, bh);
                mma16816(acc[nt], ah, bl);
                mma16816(acc[nt], al, bh);
            }
        }
    }

    // epilogue: split to bf16 hi/lo packed q/k/v; fold 0.125 into K
    u32* const GH[3] = {g_qh, g_kh, g_vh};
    u32* const GL[3] = {g_ql, g_kl, g_vl};
    const int row0 = m0 + slab * 16 + rr;
    #pragma unroll
    for (int nt = 0; nt < 12; nt++) {
        int colb = half * 96 + nt * 8;
        int mat = colb >> 6;
        int hqb = (colb & 63) >> 1;
        float s = (mat == 1) ? 0.125f : 1.f;
        float a0 = acc[nt][0] * s, a1 = acc[nt][1] * s;
        float a2 = acc[nt][2] * s, a3 = acc[nt][3] * s;
        float h0 = bfh(a0), h1 = bfh(a1), h2 = bfh(a2), h3 = bfh(a3);
        GH[mat][(size_t)row0 * 32 + hqb + q]       = pkbf(h0, h1);
        GL[mat][(size_t)row0 * 32 + hqb + q]       = pkbf(a0 - h0, a1 - h1);
        GH[mat][(size_t)(row0 + 8) * 32 + hqb + q] = pkbf(h2, h3);
        GL[mat][(size_t)(row0 + 8) * 32 + hqb + q] = pkbf(a2 - h2, a3 - h3);
    }
}

// ---------------------------------------------------------------------------
// V transpose: g_vh/g_vl -> g_vth/g_vtl ([b][h][s-pair], pairs along t).
// ---------------------------------------------------------------------------
__global__ __launch_bounds__(256) void vt_kernel()
{
    int idx = blockIdx.x * 256 + threadIdx.x;   // 8*32*1024 tasks
    int b  = idx >> 15;
    int r  = idx & 32767;
    int hq = r >> 10;           // 0..31
    int sp = r & 1023;
    const u32* vh = g_vh + (size_t)b * TT * 32;
    const u32* vl = g_vl + (size_t)b * TT * 32;
    u32 a = vh[(size_t)(2 * sp) * 32 + hq];
    u32 c = vh[(size_t)(2 * sp + 1) * 32 + hq];
    size_t ob = ((size_t)b * 64 + 2 * hq) * 1024 + sp;
    g_vth[ob]        = __byte_perm(a, c, 0x5410);
    g_vth[ob + 1024] = __byte_perm(a, c, 0x7632);
    a = vl[(size_t)(2 * sp) * 32 + hq];
    c = vl[(size_t)(2 * sp + 1) * 32 + hq];
    g_vtl[ob]        = __byte_perm(a, c, 0x5410);
    g_vtl[ob + 1024] = __byte_perm(a, c, 0x7632);
}

// ---------------------------------------------------------------------------
// Flash attention, triangle-paired CTAs + cp.async double buffering + ldmatrix.
//   CTA bx handles t-tiles (bx, 31-bx): total 33 mma-iterations each (balanced).
// ---------------------------------------------------------------------------
#define KOFF(t, l)  ((t) * 4608 + (l) * 2304)
#define QOFF(bf, l) (9216 + (bf) * 4608 + (l) * 2304)
#define VOFF(bf, l) (18432 + (bf) * 4608 + (l) * 2304)
#define ATTN_SMEM_U32 27904   // 111616 B

__device__ __forceinline__ void stage64(u32 sbyte, const u32* g, int gstride, int tid) {
    #pragma unroll
    for (int u = 0; u < 2; u++) {
        int idx = tid + u * 256;      // 512 16B chunks
        int row = idx >> 3, ch = idx & 7;
        cp16(sbyte + (u32)(row * PST + ch * 4) * 4, g + (size_t)row * gstride + ch * 4);
    }
}

__device__ __forceinline__ void online_update(
    float (&sacc)[4][4], float& m_lo, float& m_hi, float& l_lo, float& l_hi,
    float (&o)[8][4], u32 (&pah)[2][4], u32 (&pal)[2][4])
{
    float mx0 = -INFINITY, mx1 = -INFINITY;
    #pragma unroll
    for (int nt = 0; nt < 4; nt++) {
        mx0 = fmaxf(mx0, fmaxf(sacc[nt][0], sacc[nt][1]));
        mx1 = fmaxf(mx1, fmaxf(sacc[nt][2], sacc[nt][3]));
    }
    mx0 = fmaxf(mx0, __shfl_xor_sync(0xffffffffu, mx0, 1));
    mx0 = fmaxf(mx0, __shfl_xor_sync(0xffffffffu, mx0, 2));
    mx1 = fmaxf(mx1, __shfl_xor_sync(0xffffffffu, mx1, 1));
    mx1 = fmaxf(mx1, __shfl_xor_sync(0xffffffffu, mx1, 2));
    float mn0 = fmaxf(m_lo, mx0), mn1 = fmaxf(m_hi, mx1);
    float sum0 = 0.f, sum1 = 0.f;
    #pragma unroll
    for (int nt = 0; nt < 4; nt++) {
        sacc[nt][0] = __expf(fmaxf(sacc[nt][0] - mn0, -88.f));
        sacc[nt][1] = __expf(fmaxf(sacc[nt][1] - mn0, -88.f));
        sacc[nt][2] = __expf(fmaxf(sacc[nt][2] - mn1, -88.f));
        sacc[nt][3] = __expf(fmaxf(sacc[nt][3] - mn1, -88.f));
        sum0 += sacc[nt][0] + sacc[nt][1];
        sum1 += sacc[nt][2] + sacc[nt][3];
    }
    sum0 += __shfl_xor_sync(0xffffffffu, sum0, 1);
    sum0 += __shfl_xor_sync(0xffffffffu, sum0, 2);
    sum1 += __shfl_xor_sync(0xffffffffu, sum1, 1);
    sum1 += __shfl_xor_sync(0xffffffffu, sum1, 2);
    float cf0 = __expf(fmaxf(m_lo - mn0, -88.f));
    float cf1 = __expf(fmaxf(m_hi - mn1, -88.f));
    l_lo = l_lo * cf0 + sum0; l_hi = l_hi * cf1 + sum1;
    m_lo = mn0; m_hi = mn1;
    #pragma unroll
    for (int nt = 0; nt < 8; nt++) {
        o[nt][0] *= cf0; o[nt][1] *= cf0;
        o[nt][2] *= cf1; o[nt][3] *= cf1;
    }
    #pragma unroll
    for (int kp = 0; kp < 2; kp++) {
        float p00 = sacc[2*kp][0],   p01 = sacc[2*kp][1];
        float p02 = sacc[2*kp][2],   p03 = sacc[2*kp][3];
        float p10 = sacc[2*kp+1][0], p11 = sacc[2*kp+1][1];
        float p12 = sacc[2*kp+1][2], p13 = sacc[2*kp+1][3];
        float h00 = bfh(p00), h01 = bfh(p01), h02 = bfh(p02), h03 = bfh(p03);
        float h10 = bfh(p10), h11 = bfh(p11), h12 = bfh(p12), h13 = bfh(p13);
        pah[kp][0] = pkbf(h00, h01);
        pah[kp][1] = pkbf(h02, h03);
        pah[kp][2] = pkbf(h10, h11);
        pah[kp][3] = pkbf(h12, h13);
        pal[kp][0] = pkbf(p00 - h00, p01 - h01);
        pal[kp][1] = pkbf(p02 - h02, p03 - h03);
        pal[kp][2] = pkbf(p10 - h10, p11 - h11);
        pal[kp][3] = pkbf(p12 - h12, p13 - h13);
    }
}

__device__ __forceinline__ void merge_write(
    float (&o)[8][4], float m_lo, float m_hi, float l_lo, float l_hi,
    float* mlbuf, float* obuf, int slab, int half, int rr, int q,
    float* __restrict__ out, int b, int t0)
{
    __syncthreads();
    if (q == 0) {
        int base = (slab * 2 + half) * 16;
        mlbuf[(base + rr) * 2]         = m_lo;
        mlbuf[(base + rr) * 2 + 1]     = l_lo;
        mlbuf[(base + rr + 8) * 2]     = m_hi;
        mlbuf[(base + rr + 8) * 2 + 1] = l_hi;
    }
    __syncthreads();
    int ob = (slab * 2 + (1 - half)) * 16;
    float mo0 = mlbuf[(ob + rr) * 2],     lo0 = mlbuf[(ob + rr) * 2 + 1];
    float mo1 = mlbuf[(ob + rr + 8) * 2], lo1 = mlbuf[(ob + rr + 8) * 2 + 1];
    float M0 = fmaxf(m_lo, mo0), M1 = fmaxf(m_hi, mo1);
    float f0 = __expf(fmaxf(m_lo - M0, -88.f));
    float f1 = __expf(fmaxf(m_hi - M1, -88.f));
    float g0 = __expf(fmaxf(mo0 - M0, -88.f));
    float g1 = __expf(fmaxf(mo1 - M1, -88.f));
    float L0 = l_lo * f0 + lo0 * g0;
    float L1 = l_hi * f1 + lo1 * g1;
    #pragma unroll
    for (int nt = 0; nt < 8; nt++) {
        o[nt][0] *= f0; o[nt][1] *= f0;
        o[nt][2] *= f1; o[nt][3] *= f1;
    }
    if (half == 1) {
        #pragma unroll
        for (int nt = 0; nt < 8; nt++) {
            int cb = nt * 8 + 2 * q;
            obuf[(slab * 16 + rr) * 64 + cb]         = o[nt][0];
            obuf[(slab * 16 + rr) * 64 + cb + 1]     = o[nt][1];
            obuf[(slab * 16 + rr + 8) * 64 + cb]     = o[nt][2];
            obuf[(slab * 16 + rr + 8) * 64 + cb + 1] = o[nt][3];
        }
    }
    __syncthreads();
    if (half == 0) {
        float i0 = 1.f / L0, i1 = 1.f / L1;
        size_t rb = ((size_t)b * TT + t0 + slab * 16 + rr) * 64;
        #pragma unroll
        for (int nt = 0; nt < 8; nt++) {
            int cb = nt * 8 + 2 * q;
            float2 r1;
            r1.x = (o[nt][0] + obuf[(slab * 16 + rr) * 64 + cb]) * i0;
            r1.y = (o[nt][1] + obuf[(slab * 16 + rr) * 64 + cb + 1]) * i0;
            *(float2*)(out + rb + cb) = r1;
            float2 r2;
            r2.x = (o[nt][2] + obuf[(slab * 16 + rr + 8) * 64 + cb]) * i1;
            r2.y = (o[nt][3] + obuf[(slab * 16 + rr + 8) * 64 + cb + 1]) * i1;
            *(float2*)(out + rb + 8 * 64 + cb) = r2;
        }
    }
}

__global__ __launch_bounds__(256) void attn_kernel(float* __restrict__ out)
{
    extern __shared__ u32 sm[];
    float* mlbuf = (float*)(sm + 27648);
    float* obuf  = (float*)(sm + 9216);

    const int tid  = threadIdx.x;
    const int wid  = tid >> 5, lane = tid & 31;
    const int slab = wid >> 1, half = wid & 1;
    const int rr   = lane >> 2, q = lane & 3;
    const int b    = blockIdx.y;
    const int bx   = blockIdx.x;          // tile A = bx, tile B = 31-bx
    const int tB   = 31 - bx;
    const int last = tB;

    const u32 sb = smem_u32(sm);
    const int lane7 = lane & 7;
    const int arow  = lane7 + (lane & 8);
    const int acx4  = (lane & 16) ? 16 : 0;
    const int bex4  = (lane & 8) ? 16 : 0;

    u32 aK[2][2];
    #pragma unroll
    for (int t = 0; t < 2; t++) {
        aK[t][0] = sb + (u32)(KOFF(t,0) + (slab * 16 + arow) * PST) * 4 + acx4;
        aK[t][1] = sb + (u32)(KOFF(t,1) + (slab * 16 + arow) * PST) * 4 + acx4;
    }

    // stage K (both tiles) + Q/V(st=0)
    stage64(sb + (u32)KOFF(0,0) * 4, g_kh + ((size_t)b * TT + bx * 64) * 32, 32, tid);
    stage64(sb + (u32)KOFF(0,1) * 4, g_kl + ((size_t)b * TT + bx * 64) * 32, 32, tid);
    stage64(sb + (u32)KOFF(1,0) * 4, g_kh + ((size_t)b * TT + tB * 64) * 32, 32, tid);
    stage64(sb + (u32)KOFF(1,1) * 4, g_kl + ((size_t)b * TT + tB * 64) * 32, 32, tid);
    stage64(sb + (u32)QOFF(0,0) * 4, g_qh + (size_t)b * TT * 32, 32, tid);
    stage64(sb + (u32)QOFF(0,1) * 4, g_ql + (size_t)b * TT * 32, 32, tid);
    stage64(sb + (u32)VOFF(0,0) * 4, g_vth + (size_t)b * 65536, 1024, tid);
    stage64(sb + (u32)VOFF(0,1) * 4, g_vtl + (size_t)b * 65536, 1024, tid);
    cp_commit();

    float oA[8][4], oB[8][4];
    #pragma unroll
    for (int i = 0; i < 8; i++)
        #pragma unroll
        for (int j = 0; j < 4; j++) { oA[i][j] = 0.f; oB[i][j] = 0.f; }
    float mA0 = -INFINITY, mA1 = -INFINITY, lA0 = 0.f, lA1 = 0.f;
    float mB0 = -INFINITY, mB1 = -INFINITY, lB0 = 0.f, lB1 = 0.f;

    for (int st = 0; st <= last; st++) {
        const int buf = st & 1;
        cp_wait0();
        __syncthreads();
        if (st < last) {
            int nb = buf ^ 1, s1 = st + 1;
            stage64(sb + (u32)QOFF(nb,0) * 4, g_qh + ((size_t)b * TT + s1 * 64) * 32, 32, tid);
            stage64(sb + (u32)QOFF(nb,1) * 4, g_ql + ((size_t)b * TT + s1 * 64) * 32, 32, tid);
            stage64(sb + (u32)VOFF(nb,0) * 4, g_vth + (size_t)b * 65536 + s1 * 32, 1024, tid);
            stage64(sb + (u32)VOFF(nb,1) * 4, g_vtl + (size_t)b * 65536 + s1 * 32, 1024, tid);
            cp_commit();
        }
        const bool actA = (st <= bx);
        const u32 qB  = sb + (u32)(QOFF(buf,0) + (half * 32 + lane7) * PST) * 4 + bex4;
        const u32 qBl = qB + 2304 * 4;
        const u32 vB  = sb + (u32)(VOFF(buf,0) + lane7 * PST + half * 16) * 4 + bex4;
        const u32 vBl = vB + 2304 * 4;

        // ---- S for both tiles ----
        float sA[4][4], sB4[4][4];
        #pragma unroll
        for (int i = 0; i < 4; i++)
            #pragma unroll
            for (int j = 0; j < 4; j++) { sA[i][j] = 0.f; sB4[i][j] = 0.f; }
        #pragma unroll
        for (int kt = 0; kt < 4; kt++) {
            u32 ahA[4], alA[4], ahB[4], alB[4];
            if (actA) { ldm_x4(ahA, aK[0][0] + kt * 32); ldm_x4(alA, aK[0][1] + kt * 32); }
            ldm_x4(ahB, aK[1][0] + kt * 32); ldm_x4(alB, aK[1][1] + kt * 32);
            #pragma unroll
            for (int nt = 0; nt < 4; nt++) {
                u32 bh[2], bl[2];
                ldm_x2(bh, qB  + nt * (8 * PST * 4) + kt * 32);
                ldm_x2(bl, qBl + nt * (8 * PST * 4) + kt * 32);
                if (actA) {
                    mma16816(sA[nt], ahA, bh);
                    mma16816(sA[nt], ahA, bl);
                    mma16816(sA[nt], alA, bh);
                }
                mma16816(sB4[nt], ahB, bh);
                mma16816(sB4[nt], ahB, bl);
                mma16816(sB4[nt], alB, bh);
            }
        }

        const int s0 = st * 64;
        u32 pahA[2][4], palA[2][4], pahB[2][4], palB[2][4];
        if (actA) {
            if (st == bx) {   // diagonal of tile A
                int tlo = bx * 64 + slab * 16 + rr, thi = tlo + 8;
                #pragma unroll
                for (int nt = 0; nt < 4; nt++) {
                    int sc = s0 + half * 32 + nt * 8 + 2 * q;
                    if (sc > tlo)     sA[nt][0] = -INFINITY;
                    if (sc + 1 > tlo) sA[nt][1] = -INFINITY;
                    if (sc > thi)     sA[nt][2] = -INFINITY;
                    if (sc + 1 > thi) sA[nt][3] = -INFINITY;
                }
            }
            online_update(sA, mA0, mA1, lA0, lA1, oA, pahA, palA);
        }
        if (st == tB) {       // diagonal of tile B
            int tlo = tB * 64 + slab * 16 + rr, thi = tlo + 8;
            #pragma unroll
            for (int nt = 0; nt < 4; nt++) {
                int sc = s0 + half * 32 + nt * 8 + 2 * q;
                if (sc > tlo)     sB4[nt][0] = -INFINITY;
                if (sc + 1 > tlo) sB4[nt][1] = -INFINITY;
                if (sc > thi)     sB4[nt][2] = -INFINITY;
                if (sc + 1 > thi) sB4[nt][3] = -INFINITY;
            }
        }
        online_update(sB4, mB0, mB1, lB0, lB1, oB, pahB, palB);

        // ---- O += P.V (V fragments shared between tiles) ----
        #pragma unroll
        for (int kp = 0; kp < 2; kp++) {
            #pragma unroll
            for (int nt = 0; nt < 8; nt++) {
                u32 vh2[2], vl2[2];
                ldm_x2(vh2, vB  + nt * (8 * PST * 4) + kp * 32);
                ldm_x2(vl2, vBl + nt * (8 * PST * 4) + kp * 32);
                if (actA) {
                    mma16816(oA[nt], pahA[kp], vh2);
                    mma16816(oA[nt], pahA[kp], vl2);
                    mma16816(oA[nt], palA[kp], vh2);
                }
                mma16816(oB[nt], pahB[kp], vh2);
                mma16816(oB[nt], pahB[kp], vl2);
                mma16816(oB[nt], palB[kp], vh2);
            }
        }
    }

    merge_write(oA, mA0, mA1, lA0, lA1, mlbuf, obuf, slab, half, rr, q, out, b, bx * 64);
    merge_write(oB, mB0, mB1, lB0, lB1, mlbuf, obuf, slab, half, rr, q, out, b, tB * 64);
}

// ---------------------------------------------------------------------------
extern "C" void kernel_launch(void* const* d_in, const int* in_sizes, int n_in,
                              void* d_out, int out_size)
{
    const float* x  = (const float*)d_in[0];
    const float* Wq = (const float*)d_in[1];
    const float* Wk = (const float*)d_in[2];
    const float* Wv = (const float*)d_in[3];
    float* out = (float*)d_out;

    prep_w_kernel<<<384, 256>>>(Wq, Wk, Wv);

    cudaFuncSetAttribute(proj_kernel,
                         cudaFuncAttributeMaxDynamicSharedMemorySize,
                         PROJ_SMEM_U32 * 4);
    proj_kernel<<<BT / 64, 256, PROJ_SMEM_U32 * 4>>>(x);

    vt_kernel<<<1024, 256>>>();

    cudaFuncSetAttribute(attn_kernel,
                         cudaFuncAttributeMaxDynamicSharedMemorySize,
                         ATTN_SMEM_U32 * 4);
    dim3 grid(16, BB);
    attn_kernel<<<grid, 256, ATTN_SMEM_U32 * 4>>>(out);
}